// round 7
// baseline (speedup 1.0000x reference)
#include <cuda_runtime.h>

#define DEPTH    512
#define NPAIR    255        // pairs 0..254 real; cols 510,511 zero PE
#define VOCAB    198
#define RPB      448        // rows per block
#define THREADS  1024       // 32 warps; warp w handles rows w, w+32, ...
#define QTR4     32         // float4s per depth quarter (128 floats)

struct F2 { float x, y; };

// ---------------------------------------------------------------------------
// constexpr double-precision math (compile-time only)
// ---------------------------------------------------------------------------
constexpr double kTwoPiHi = 6.283185307179586;
constexpr double kTwoPiLo = 2.4492935982947064e-16;

constexpr double d_exp(double x) {          // x in [-9.3, 0]
    double y = x / 128.0;
    double t = 1.0 + y * (1.0 + y * (1.0/2 + y * (1.0/6 + y * (1.0/24 +
               y * (1.0/120 + y * (1.0/720 + y * (1.0/5040)))))));
    for (int i = 0; i < 7; ++i) t *= t;
    return t;
}
constexpr double d_reduce(double x) {       // x >= 0 -> [-pi, pi]
    long long n = (long long)(x / kTwoPiHi + 0.5);
    return (x - (double)n * kTwoPiHi) - (double)n * kTwoPiLo;
}
constexpr double d_sin(double x) {
    double r = d_reduce(x), r2 = r * r;
    double t = 1.0 - r2 / 342.0;
    t = 1.0 - r2 / 272.0 * t;
    t = 1.0 - r2 / 210.0 * t;
    t = 1.0 - r2 / 156.0 * t;
    t = 1.0 - r2 / 110.0 * t;
    t = 1.0 - r2 / 72.0  * t;
    t = 1.0 - r2 / 42.0  * t;
    t = 1.0 - r2 / 20.0  * t;
    t = 1.0 - r2 / 6.0   * t;
    return r * t;
}
constexpr double d_cos(double x) {
    double r = d_reduce(x), r2 = r * r;
    double t = 1.0 - r2 / 380.0;
    t = 1.0 - r2 / 306.0 * t;
    t = 1.0 - r2 / 240.0 * t;
    t = 1.0 - r2 / 182.0 * t;
    t = 1.0 - r2 / 132.0 * t;
    t = 1.0 - r2 / 90.0  * t;
    t = 1.0 - r2 / 56.0  * t;
    t = 1.0 - r2 / 30.0  * t;
    t = 1.0 - r2 / 12.0  * t;
    t = 1.0 - r2 / 2.0   * t;
    return t;
}

// phasor(q * STRIDE * w_j), q in [0, COUNT), j in [0, 256). Tail j>=NPAIR -> (0, TAILC).
template<int STRIDE, int COUNT, int TAILC>
struct alignas(16) TableGen {
    F2 v[COUNT * 256];
    constexpr TableGen() : v() {
        for (int q = 0; q < COUNT; ++q) {
            for (int j = 0; j < 256; ++j) {
                F2& e = v[q * 256 + j];
                if (j >= NPAIR) { e.x = 0.f; e.y = (float)TAILC; }
                else {
                    double w = d_exp(-9.210340371976184 * (double)j / 256.0);
                    double a = (double)q * (double)STRIDE * w;
                    e.x = (float)d_sin(a);
                    e.y = (float)d_cos(a);
                }
            }
        }
    }
};

// chunk < 320 supported (L <= 143360): chunk = qh*32 + ql
__device__ const TableGen<14336, 10, 1> c_T1{};  // phasor(qh * 32*448 * w_j)
__device__ const TableGen<448,   32, 1> c_T2{};  // phasor(ql * 448    * w_j)
__device__ const TableGen<1,     32, 0> c_Tw{};  // phasor(w * w_j); zero tail
__device__ const TableGen<32,     2, 1> c_S32{}; // slot 1 = phasor(32 * w_j)

__device__ __forceinline__ float2 cmul(float2 a, float2 b)
{   // (sin,cos) angle addition
    return make_float2(fmaf(a.x, b.y,  a.y * b.x),
                       fmaf(a.y, b.y, -a.x * b.x));
}

// ---------------------------------------------------------------------------
// Main: grid = 4 * nchunks, quarter-major (bid = q * nchunks + chunk).
// Block: 448 rows x one 128-col depth quarter. Wordlist quarter-slice
// (101 KB) staged in SMEM -> gathers are conflict-free LDS.128;
// L1 carries only the store stream. 2 CTAs/SM (103 KB smem each).
// ---------------------------------------------------------------------------
__global__ __launch_bounds__(THREADS, 2)
void emb_pe_kernel(const int* __restrict__ idx,
                   const float4* __restrict__ wl4,   // [VOCAB][128] float4
                   float4* __restrict__ out4,        // [L][128] float4
                   int L, int nchunks)
{
    extern __shared__ char smem[];
    int*    sh_idx = (int*)smem;                        // [RPB]
    float4* sh_wl  = (float4*)(smem + RPB * 4);         // [VOCAB][32]

    const int bid   = blockIdx.x;
    const int q     = bid / nchunks;                    // depth quarter 0..3
    const int chunk = bid - q * nchunks;
    const int row0  = chunk * RPB;
    const int nrows = min(RPB, L - row0);
    const int tid   = threadIdx.x;
    const int w     = tid >> 5;                         // warp id 0..31
    const int l     = tid & 31;                         // lane = float4 col in quarter

    // stage wordlist quarter-slice (coalesced 512 B per warp)
    #pragma unroll
    for (int i = tid; i < VOCAB * QTR4; i += THREADS) {
        int vr = i >> 5, c = i & 31;
        sh_wl[i] = __ldg(&wl4[vr * (DEPTH / 4) + q * QTR4 + c]);
    }
    for (int i = tid; i < nrows; i += THREADS)
        sh_idx[i] = idx[row0 + i];
    __syncthreads();

    // pair-pair index: this thread's float4 covers pairs j0 = 2*k2, j1 = j0+1
    const int k2 = q * QTR4 + l;                        // 0..127

    const float4* t1 = reinterpret_cast<const float4*>(c_T1.v);
    const float4* t2 = reinterpret_cast<const float4*>(c_T2.v);
    const float4* tw = reinterpret_cast<const float4*>(c_Tw.v);
    const float4* ts = reinterpret_cast<const float4*>(c_S32.v);

    float4 A = t1[(chunk >> 5) * 128 + k2];             // {s_j0,c_j0,s_j1,c_j1}
    float4 B = t2[(chunk & 31) * 128 + k2];
    float4 W = tw[w * 128 + k2];
    float4 S = ts[128 + k2];                            // slot 1: step phasor(32 w)

    float2 P0 = cmul(cmul(make_float2(A.x, A.y), make_float2(B.x, B.y)),
                     make_float2(W.x, W.y));
    float2 P1 = cmul(cmul(make_float2(A.z, A.w), make_float2(B.z, B.w)),
                     make_float2(W.z, W.w));

    float s0 = P0.x, c0 = P0.y, s1 = P1.x, c1 = P1.y;

    float4* outp = out4 + (size_t)(row0 + w) * (DEPTH / 4) + k2;

    #pragma unroll 7
    for (int r = w; r < nrows; r += 32) {
        int token = sh_idx[r];                          // broadcast within warp
        float4 e = sh_wl[token * QTR4 + l];             // conflict-free LDS.128
        float4 o;
        o.x = e.x + s0;
        o.y = e.y + c0;
        o.z = e.z + s1;
        o.w = e.w + c1;
        __stcs(outp, o);
        outp += 32 * (DEPTH / 4);

        float ns0 = fmaf(s0, S.y,  c0 * S.x);
        float nc0 = fmaf(c0, S.y, -s0 * S.x);
        float ns1 = fmaf(s1, S.w,  c1 * S.z);
        float nc1 = fmaf(c1, S.w, -s1 * S.z);
        s0 = ns0; c0 = nc0; s1 = ns1; c1 = nc1;
    }
}

extern "C" void kernel_launch(void* const* d_in, const int* in_sizes, int n_in,
                              void* d_out, int out_size)
{
    const int*   idx = (const int*)d_in[0];
    const float* wl  = (const float*)d_in[1];
    float*       out = (float*)d_out;

    int L       = in_sizes[0];
    int nchunks = (L + RPB - 1) / RPB;

    size_t smem_bytes = (size_t)RPB * 4 + (size_t)VOCAB * QTR4 * 16;  // 103168
    static int attr_done = 0;
    cudaFuncSetAttribute(emb_pe_kernel,
                         cudaFuncAttributeMaxDynamicSharedMemorySize,
                         (int)smem_bytes);
    (void)attr_done;

    emb_pe_kernel<<<4 * nchunks, THREADS, smem_bytes>>>(idx, (const float4*)wl,
                                                        (float4*)out, L, nchunks);
}